// round 6
// baseline (speedup 1.0000x reference)
#include <cuda_runtime.h>

// Voronoi nearest-site via fine-grid candidate LUT. Reference-exact fp32:
//   a  = rn(rn(x0^2) + rn(x1^2))
//   e  = fmaf(x1, sy, rn(x0*sx))
//   d2 = rn(rn(a - 2*e) + cs),  cs = rn(rn(sx^2) + rn(sy^2))
//   argmin: ascending scan, strict <
//
// R5 -> R6:
//  * build uses a 4-subcenter band test (band halved: sqrt(2)/(2*GR)) ->
//    far fewer multi-candidate and >4-candidate cells.
//  * >4-cand fallback scans only the 5x5 coarse neighborhood (<=25 sites,
//    ids computed, ascending; provably contains any site the reference's
//    noisy argmin can select) instead of all 100.
//  * multi path = branchless exactly-4 evals (entries padded with id0;
//    duplicates can't win under strict <). Single-cand fast path kept.

#define GR 88
#define NS 100
#define NCELL (GR * GR)

__device__ unsigned int g_grid[NCELL];
__device__ float4 g_cand[NS];   // sx, sy, cs, 0
__device__ float4 g_rgb[NS];    // r, g, b, 0

__global__ void build_lut(const float* __restrict__ p) {
    __shared__ float sp[2 * NS];
    if (threadIdx.x < NS) {
        sp[2 * threadIdx.x + 0] = p[1 + 5 * threadIdx.x];
        sp[2 * threadIdx.x + 1] = p[2 + 5 * threadIdx.x];
    }
    __syncthreads();

    int cell = blockIdx.x * blockDim.x + threadIdx.x;
    if (cell < NS) {
        float sx = sp[2 * cell], sy = sp[2 * cell + 1];
        float cs = __fadd_rn(__fmul_rn(sx, sx), __fmul_rn(sy, sy));
        g_cand[cell] = make_float4(sx, sy, cs, 0.0f);
        g_rgb[cell]  = make_float4(p[3 + 5 * cell], p[4 + 5 * cell], p[5 + 5 * cell], 0.0f);
    }
    if (cell >= NCELL) return;

    int gy = cell / GR;
    int gx = cell - gy * GR;

    // 4 sub-quadrant centers of the cell. Any p in the cell is within
    // L2 distance sqrt(2)/(4*GR) of one of them; Lipschitz factor 2 =>
    // include s iff exists q: d(q,s) <= m(q) + sqrt(2)/(2*GR) + slack.
    float qx[4], qy[4];
    {
        float x0 = (gx + 0.25f) * (1.0f / GR), x1 = (gx + 0.75f) * (1.0f / GR);
        float y0 = (gy + 0.25f) * (1.0f / GR), y1 = (gy + 0.75f) * (1.0f / GR);
        qx[0] = x0; qy[0] = y0;  qx[1] = x1; qy[1] = y0;
        qx[2] = x0; qy[2] = y1;  qx[3] = x1; qy[3] = y1;
    }

    // m(q_k): nearest distance from each subcenter.
    float m[4] = {3.4e38f, 3.4e38f, 3.4e38f, 3.4e38f};
    for (int s = 0; s < NS; s++) {
        float sx = sp[2 * s], sy = sp[2 * s + 1];
        #pragma unroll
        for (int k = 0; k < 4; k++) {
            float dx = qx[k] - sx, dy = qy[k] - sy;
            m[k] = fminf(m[k], fmaf(dx, dx, dy * dy));
        }
    }
    float thr[4];
    const float band = 0.0080349f + 1e-4f;   // sqrt(2)/(2*88) + slack
    #pragma unroll
    for (int k = 0; k < 4; k++) {
        float t = sqrtf(m[k]) + band;
        thr[k] = t * t;
    }

    unsigned int ids[4] = {0, 0, 0, 0};
    int cnt = 0;
    for (int s = 0; s < NS; s++) {
        float sx = sp[2 * s], sy = sp[2 * s + 1];
        bool inc = false;
        #pragma unroll
        for (int k = 0; k < 4; k++) {
            float dx = qx[k] - sx, dy = qy[k] - sy;
            inc |= (fmaf(dx, dx, dy * dy) <= thr[k]);
        }
        if (inc) {
            if (cnt < 4) ids[cnt] = (unsigned int)s;
            cnt++;
        }
    }

    unsigned int entry;
    if (cnt > 4) {
        entry = 0x0000FE00u;                                   // 5x5 fallback
    } else if (cnt <= 1) {
        entry = ids[0] | 0xFFFFFF00u;                          // single: fast path
    } else {
        for (int k = cnt; k < 4; k++) ids[k] = ids[0];         // pad (can't win)
        entry = ids[0] | (ids[1] << 8) | (ids[2] << 16) | (ids[3] << 24);
    }
    g_grid[cell] = entry;
}

struct SmemTables {
    unsigned int grid[NCELL];   // 30976 B
    float4 cand[NS];            //  1600 B
    float4 rgb[NS];             //  1600 B
};

__device__ __forceinline__ float4 lookup_one(
    float px, float py,
    const unsigned int* __restrict__ sgrid,
    const float4* __restrict__ scand,
    const float4* __restrict__ srgb)
{
    int cx = (int)(px * (float)GR);   // x in [0,1): no clamp needed
    int cy = (int)(py * (float)GR);
    unsigned int e = sgrid[cy * GR + cx];

    int idx;
    if ((e >> 8) == 0x00FFFFFFu) {
        idx = (int)(e & 0xFFu);                         // single candidate
    } else {
        float a = __fadd_rn(__fmul_rn(px, px), __fmul_rn(py, py));
        float bd = 3.4e38f;
        int bi = 0;
        if (((e >> 8) & 0xFFu) == 0xFEu) {
            // Rare: 5x5 coarse-neighborhood scan (ascending site ids).
            int ci = (int)(px * 10.0f);
            int cj = (int)(py * 10.0f);
            int i1 = min(9, ci + 2), j0 = max(0, cj - 2), j1 = min(9, cj + 2);
            for (int ii = max(0, ci - 2); ii <= i1; ii++) {
                for (int jj = j0; jj <= j1; jj++) {
                    int s = ii * 10 + jj;
                    float4 c = scand[s];
                    float ee = __fmaf_rn(py, c.y, __fmul_rn(px, c.x));
                    float d2 = __fadd_rn(__fsub_rn(a, __fmul_rn(2.0f, ee)), c.z);
                    if (d2 < bd) { bd = d2; bi = s; }
                }
            }
        } else {
            // Branchless exactly-4 evaluation (padded entries).
            #pragma unroll
            for (int k = 0; k < 4; k++) {
                unsigned int c = (e >> (8 * k)) & 0xFFu;
                float4 s = scand[c];
                float ee = __fmaf_rn(py, s.y, __fmul_rn(px, s.x));
                float d2 = __fadd_rn(__fsub_rn(a, __fmul_rn(2.0f, ee)), s.z);
                if (d2 < bd) { bd = d2; bi = (int)c; }
            }
        }
        idx = bi;
    }
    return srgb[idx];
}

__global__ void __launch_bounds__(256, 6) voronoi_main(
    const float2* __restrict__ x, float* __restrict__ out, int n)
{
    __shared__ SmemTables st;

    {
        const uint4* gg = (const uint4*)g_grid;
        uint4* sg = (uint4*)st.grid;
        for (int i = threadIdx.x; i < NCELL / 4; i += 256) sg[i] = gg[i];
        if (threadIdx.x < NS) {
            st.cand[threadIdx.x] = g_cand[threadIdx.x];
            st.rgb[threadIdx.x]  = g_rgb[threadIdx.x];
        }
    }
    __syncthreads();

    int tid = blockIdx.x * blockDim.x + threadIdx.x;
    int stride = gridDim.x * blockDim.x;

    int i = tid;
    for (; i + stride < n; i += 2 * stride) {
        int j = i + stride;
        float2 p0 = x[i];
        float2 p1 = x[j];

        float4 c0 = lookup_one(p0.x, p0.y, st.grid, st.cand, st.rgb);
        float4 c1 = lookup_one(p1.x, p1.y, st.grid, st.cand, st.rgb);

        out[3 * i + 0] = c0.x;
        out[3 * i + 1] = c0.y;
        out[3 * i + 2] = c0.z;
        out[3 * j + 0] = c1.x;
        out[3 * j + 1] = c1.y;
        out[3 * j + 2] = c1.z;
    }
    if (i < n) {
        float2 p0 = x[i];
        float4 c0 = lookup_one(p0.x, p0.y, st.grid, st.cand, st.rgb);
        out[3 * i + 0] = c0.x;
        out[3 * i + 1] = c0.y;
        out[3 * i + 2] = c0.z;
    }
}

extern "C" void kernel_launch(void* const* d_in, const int* in_sizes, int n_in,
                              void* d_out, int out_size) {
    const float2* x = (const float2*)d_in[0];
    const float*  p = (const float*)d_in[1];
    float* out = (float*)d_out;
    int n = in_sizes[0] / 2;

    build_lut<<<(NCELL + 255) / 256, 256>>>(p);
    voronoi_main<<<888, 256>>>(x, out, n);
}